// round 3
// baseline (speedup 1.0000x reference)
#include <cuda_runtime.h>
#include <cuda_bf16.h>

// ---------------------------------------------------------------------------
// SafetyLayer: per-car separable QP projection.
//   Kernel 1 (512 thr): per-column QP bounds -> 6x512 floats of params.
//   Kernel 2: streaming rows x 512 fp32. Each thread owns ONE column-vector
//   (float4 of 4 adjacent columns) and strides down rows; the 6 param
//   float4s hoist into registers, the loop is pure load-x / store-out.
// ---------------------------------------------------------------------------

#define D_COLS      512
#define NVEC_COLS   (D_COLS / 4)     // 128 float4 columns per row

// config constants
#define C_FINAL_SOC 0.97f
#define C_AC_MAX    0.165f           // 6.6/40
#define C_AD_MAG    0.165f
#define C_ETA_C     0.95f
#define C_ETA_D     0.95f
#define C_INV_ETA_C (1.0f/0.95f)
#define C_INV_ETA_D (1.0f/0.95f)
#define C_LSLOPE    0.15675f         // 6.6*0.95/40
#define C_KSLOPE    0.10263157894736841f   // 1/eta_d - eta_c
#define C_INV_KSLOPE (1.0f/C_KSLOPE)
#define C_INV_ED_KS (1.0f/0.0975f)   // 1/(eta_d*kslope); 0.0975 = 1-0.95^2 exact

// Per-column parameter planes: [0]=y_min [1]=y_max [2]=a [3]=b [4]=ad_lo [5]=act
__device__ float g_params[6 * D_COLS];

__global__ void sl_precompute(const float* __restrict__ t_rem,
                              const float* __restrict__ soc_t,
                              const float* __restrict__ t_dis,
                              const float* __restrict__ soc_dis) {
    int j = blockIdx.x * blockDim.x + threadIdx.x;
    if (j >= D_COLS) return;

    float tr  = t_rem[j];
    float st  = soc_t[j];
    float td  = t_dis[j];
    float sd  = soc_dis[j];

    bool active  = tr > 0.0f;
    bool can_dis = td > 0.0f;

    float ad_lo = can_dis ? -fminf(C_AD_MAG, C_ETA_D * sd) : 0.0f;

    float L = fminf(fmaxf(C_FINAL_SOC - (tr - 1.0f) * C_LSLOPE, 0.0f), C_FINAL_SOC);

    // y_max: reduce AD first
    float s_hi   = st + C_ETA_C * C_AC_MAX;
    float excess = fmaxf(s_hi - C_FINAL_SOC, 0.0f);
    float ad_red = fminf(excess * C_ETA_D, -ad_lo);
    float rem    = fmaxf(excess - ad_red * C_INV_ETA_D, 0.0f);
    float ac_hi  = fmaxf(C_AC_MAX - rem * C_INV_ETA_C, 0.0f);
    float y_max  = ac_hi - ad_red;

    // y_min: minimize AC+AD subject to SOC1 >= L
    float s_lo    = st + ad_lo * C_INV_ETA_D;
    float deficit = fmaxf(L - s_lo, 0.0f);
    float ad_inc  = fminf(deficit * C_ETA_D, -ad_lo);
    float rem2    = fmaxf(deficit - ad_inc * C_INV_ETA_D, 0.0f);
    float ac_lo   = fminf(rem2 * C_INV_ETA_C, C_AC_MAX);
    float y_min   = fminf(ac_lo + ad_lo + ad_inc, y_max);

    // decomposition affine constants:
    //   (soc_t + y/eta_d - U)/kslope = a + y*C_INV_ED_KS
    //   (soc_t + y/eta_d - L)/kslope = b + y*C_INV_ED_KS
    float a = (st - C_FINAL_SOC) * C_INV_KSLOPE;
    float b = (st - L)           * C_INV_KSLOPE;

    g_params[0 * D_COLS + j] = y_min;
    g_params[1 * D_COLS + j] = y_max;
    g_params[2 * D_COLS + j] = a;
    g_params[3 * D_COLS + j] = b;
    g_params[4 * D_COLS + j] = ad_lo;
    g_params[5 * D_COLS + j] = active ? 1.0f : 0.0f;
}

__device__ __forceinline__ float sl_elem(float x, float ymn, float ymx,
                                         float a, float b, float adlo, float act) {
    float y  = fminf(fmaxf(x, ymn), ymx);
    float t  = y * C_INV_ED_KS;
    float ac = fmaxf(fmaxf(y, 0.0f), t + a);
    ac = fminf(ac, fminf(C_AC_MAX, y - adlo));
    ac = fminf(ac, t + b);
    ac = fmaxf(ac, 0.0f);
    return ac * act;
}

__device__ __forceinline__ float4 sl_vec(float4 xv, float4 mn, float4 mx,
                                         float4 aa, float4 bb, float4 al, float4 ak) {
    float4 o;
    o.x = sl_elem(xv.x, mn.x, mx.x, aa.x, bb.x, al.x, ak.x);
    o.y = sl_elem(xv.y, mn.y, mx.y, aa.y, bb.y, al.y, ak.y);
    o.z = sl_elem(xv.z, mn.z, mx.z, aa.z, bb.z, al.z, ak.z);
    o.w = sl_elem(xv.w, mn.w, mx.w, aa.w, bb.w, al.w, ak.w);
    return o;
}

// grid*block threads must be a multiple of NVEC_COLS.
__global__ void __launch_bounds__(256) sl_main(const float4* __restrict__ x,
                                               float4* __restrict__ out,
                                               int n_rows) {
    int tid   = blockIdx.x * blockDim.x + threadIdx.x;
    int p     = tid & (NVEC_COLS - 1);            // fixed column-vector
    int row0  = tid >> 7;                          // starting row
    int rstep = (gridDim.x * blockDim.x) >> 7;    // row stride

    // hoist params into registers (L1-resident, loaded once per thread)
    float4 mn = ((const float4*)&g_params[0 * D_COLS])[p];
    float4 mx = ((const float4*)&g_params[1 * D_COLS])[p];
    float4 aa = ((const float4*)&g_params[2 * D_COLS])[p];
    float4 bb = ((const float4*)&g_params[3 * D_COLS])[p];
    float4 al = ((const float4*)&g_params[4 * D_COLS])[p];
    float4 ak = ((const float4*)&g_params[5 * D_COLS])[p];

    int r = row0;
    // 2-row unrolled main loop: two independent LDG.128 in flight per thread
    for (; r + rstep < n_rows; r += 2 * rstep) {
        int v0 = r * NVEC_COLS + p;
        int v1 = (r + rstep) * NVEC_COLS + p;
        float4 x0 = x[v0];
        float4 x1 = x[v1];
        out[v0] = sl_vec(x0, mn, mx, aa, bb, al, ak);
        out[v1] = sl_vec(x1, mn, mx, aa, bb, al, ak);
    }
    if (r < n_rows) {
        int v = r * NVEC_COLS + p;
        out[v] = sl_vec(x[v], mn, mx, aa, bb, al, ak);
    }
}

extern "C" void kernel_launch(void* const* d_in, const int* in_sizes, int n_in,
                              void* d_out, int out_size) {
    const float* x       = (const float*)d_in[0];
    const float* t_rem   = (const float*)d_in[1];
    const float* soc_t   = (const float*)d_in[2];
    const float* t_dis   = (const float*)d_in[3];
    const float* soc_dis = (const float*)d_in[4];
    float* out = (float*)d_out;

    int n_rows = in_sizes[0] / D_COLS;   // 32768 for the canonical shape

    sl_precompute<<<2, 256>>>(t_rem, soc_t, t_dis, soc_dis);

    // 2048 blocks x 256 thr = 524288 threads = 4096 row-threads x 128 cols
    // -> 8 row-iterations per thread (4 unrolled pairs).
    sl_main<<<2048, 256>>>((const float4*)x, (float4*)out, n_rows);
}

// round 7
// speedup vs baseline: 1.0660x; 1.0660x over previous
#include <cuda_runtime.h>
#include <cuda_bf16.h>

// ---------------------------------------------------------------------------
// SafetyLayer: per-car separable QP projection — single fused kernel.
//   Each thread owns ONE float4 column-vector (4 adjacent columns of D=512),
//   computes its per-column QP bounds inline (16 L1-broadcast floats), then
//   streams down rows with a 4x-unrolled load-x / clip / decompose / store
//   loop. Pure HBM streaming after the prologue. Single graph node.
// ---------------------------------------------------------------------------

#define D_COLS      512
#define NVEC_COLS   (D_COLS / 4)     // 128 float4 columns per row

// config constants
#define C_FINAL_SOC 0.97f
#define C_AC_MAX    0.165f           // 6.6/40
#define C_AD_MAG    0.165f
#define C_ETA_C     0.95f
#define C_ETA_D     0.95f
#define C_INV_ETA_C (1.0f/0.95f)
#define C_INV_ETA_D (1.0f/0.95f)
#define C_LSLOPE    0.15675f         // 6.6*0.95/40
#define C_KSLOPE    0.10263157894736841f   // 1/eta_d - eta_c
#define C_INV_KSLOPE (1.0f/C_KSLOPE)
#define C_INV_ED_KS (1.0f/0.0975f)   // 1/(eta_d*kslope); 0.0975 = 1-0.95^2 exact

// per-column QP bound + decomposition params (one scalar column)
__device__ __forceinline__ void col_params(float tr, float st, float td, float sd,
                                           float& ymn, float& ymx,
                                           float& a, float& b,
                                           float& adlo, float& act) {
    bool active  = tr > 0.0f;
    bool can_dis = td > 0.0f;

    adlo = can_dis ? -fminf(C_AD_MAG, C_ETA_D * sd) : 0.0f;

    float L = fminf(fmaxf(C_FINAL_SOC - (tr - 1.0f) * C_LSLOPE, 0.0f), C_FINAL_SOC);

    // y_max: reduce AD first
    float s_hi   = st + C_ETA_C * C_AC_MAX;
    float excess = fmaxf(s_hi - C_FINAL_SOC, 0.0f);
    float ad_red = fminf(excess * C_ETA_D, -adlo);
    float rem    = fmaxf(excess - ad_red * C_INV_ETA_D, 0.0f);
    float ac_hi  = fmaxf(C_AC_MAX - rem * C_INV_ETA_C, 0.0f);
    ymx          = ac_hi - ad_red;

    // y_min: minimize AC+AD subject to SOC1 >= L
    float s_lo    = st + adlo * C_INV_ETA_D;
    float deficit = fmaxf(L - s_lo, 0.0f);
    float ad_inc  = fminf(deficit * C_ETA_D, -adlo);
    float rem2    = fmaxf(deficit - ad_inc * C_INV_ETA_D, 0.0f);
    float ac_lo   = fminf(rem2 * C_INV_ETA_C, C_AC_MAX);
    ymn           = fminf(ac_lo + adlo + ad_inc, ymx);

    // decomposition affine constants:
    //   (soc_t + y/eta_d - U)/kslope = a + y*C_INV_ED_KS
    //   (soc_t + y/eta_d - L)/kslope = b + y*C_INV_ED_KS
    a = (st - C_FINAL_SOC) * C_INV_KSLOPE;
    b = (st - L)           * C_INV_KSLOPE;

    act = active ? 1.0f : 0.0f;
}

__device__ __forceinline__ float sl_elem(float x, float ymn, float ymx,
                                         float a, float b, float adlo, float act) {
    float y  = fminf(fmaxf(x, ymn), ymx);
    float t  = y * C_INV_ED_KS;
    float ac = fmaxf(fmaxf(y, 0.0f), t + a);
    ac = fminf(ac, fminf(C_AC_MAX, y - adlo));
    ac = fminf(ac, t + b);
    ac = fmaxf(ac, 0.0f);
    return ac * act;
}

__device__ __forceinline__ float4 sl_vec(float4 xv, const float4& mn, const float4& mx,
                                         const float4& aa, const float4& bb,
                                         const float4& al, const float4& ak) {
    float4 o;
    o.x = sl_elem(xv.x, mn.x, mx.x, aa.x, bb.x, al.x, ak.x);
    o.y = sl_elem(xv.y, mn.y, mx.y, aa.y, bb.y, al.y, ak.y);
    o.z = sl_elem(xv.z, mn.z, mx.z, aa.z, bb.z, al.z, ak.z);
    o.w = sl_elem(xv.w, mn.w, mx.w, aa.w, bb.w, al.w, ak.w);
    return o;
}

// grid*block threads must be a multiple of NVEC_COLS (128).
__global__ void __launch_bounds__(256) sl_fused(const float4* __restrict__ x,
                                                float4* __restrict__ out,
                                                const float4* __restrict__ t_rem4,
                                                const float4* __restrict__ soc_t4,
                                                const float4* __restrict__ t_dis4,
                                                const float4* __restrict__ soc_dis4,
                                                int n_rows) {
    int tid   = blockIdx.x * blockDim.x + threadIdx.x;
    int p     = tid & (NVEC_COLS - 1);            // fixed column-vector
    int row0  = tid >> 7;                          // starting row
    int rstep = (gridDim.x * blockDim.x) >> 7;    // row stride

    // inline per-column params (L1-broadcast loads, computed once per thread)
    float4 tr = t_rem4[p];
    float4 st = soc_t4[p];
    float4 td = t_dis4[p];
    float4 sd = soc_dis4[p];

    float4 mn, mx, aa, bb, al, ak;
    col_params(tr.x, st.x, td.x, sd.x, mn.x, mx.x, aa.x, bb.x, al.x, ak.x);
    col_params(tr.y, st.y, td.y, sd.y, mn.y, mx.y, aa.y, bb.y, al.y, ak.y);
    col_params(tr.z, st.z, td.z, sd.z, mn.z, mx.z, aa.z, bb.z, al.z, ak.z);
    col_params(tr.w, st.w, td.w, sd.w, mn.w, mx.w, aa.w, bb.w, al.w, ak.w);

    int r = row0;
    // 4-row unrolled main loop: four independent LDG.128 in flight per thread
    for (; r + 3 * rstep < n_rows; r += 4 * rstep) {
        int v0 = r * NVEC_COLS + p;
        int v1 = v0 + rstep * NVEC_COLS;
        int v2 = v1 + rstep * NVEC_COLS;
        int v3 = v2 + rstep * NVEC_COLS;
        float4 x0 = x[v0];
        float4 x1 = x[v1];
        float4 x2 = x[v2];
        float4 x3 = x[v3];
        out[v0] = sl_vec(x0, mn, mx, aa, bb, al, ak);
        out[v1] = sl_vec(x1, mn, mx, aa, bb, al, ak);
        out[v2] = sl_vec(x2, mn, mx, aa, bb, al, ak);
        out[v3] = sl_vec(x3, mn, mx, aa, bb, al, ak);
    }
    for (; r < n_rows; r += rstep) {
        int v = r * NVEC_COLS + p;
        out[v] = sl_vec(x[v], mn, mx, aa, bb, al, ak);
    }
}

extern "C" void kernel_launch(void* const* d_in, const int* in_sizes, int n_in,
                              void* d_out, int out_size) {
    const float* x       = (const float*)d_in[0];
    const float* t_rem   = (const float*)d_in[1];
    const float* soc_t   = (const float*)d_in[2];
    const float* t_dis   = (const float*)d_in[3];
    const float* soc_dis = (const float*)d_in[4];
    float* out = (float*)d_out;

    int n_rows = in_sizes[0] / D_COLS;   // 32768 for the canonical shape

    // Known-good geometry from the measured 20.5us sl_main run:
    // 2048 blocks x 256 thr = 524288 threads = 4096 row-threads x 128 cols
    // -> 8 row-iterations per thread (2 unrolled quads).
    sl_fused<<<2048, 256>>>((const float4*)x, (float4*)out,
                            (const float4*)t_rem, (const float4*)soc_t,
                            (const float4*)t_dis, (const float4*)soc_dis,
                            n_rows);
}